// round 3
// baseline (speedup 1.0000x reference)
#include <cuda_runtime.h>
#include <math.h>

// Problem constants (fixed shapes from reference)
#define D_MODEL 1280
#define NHEAD   20
#define DHEAD   64
#define BATCH   4
#define SEQ     1024
#define BHEADS  (BATCH*NHEAD)      // 80
#define M_TOTAL (BATCH*SEQ)        // 4096
#define ALPHA_C 0.48f
#define SM_SCALE 0.125f            // 1/sqrt(64)

// Scratch (device globals: no allocation allowed in kernel_launch)
__device__ float g_q[M_TOTAL * D_MODEL];
__device__ float g_k[M_TOTAL * D_MODEL];
__device__ float g_v[M_TOTAL * D_MODEL];
__device__ float g_ctx[M_TOTAL * D_MODEL];

// ---------------------------------------------------------------------------
// SGEMM: C[M,N] = A[M,K] @ B[K,N] (+ bias). 128x128 block tile, BK=16,
// 256 threads, 8x8 microtile with 2x2 split (rows ty*4 / 64+ty*4, cols
// tx*4 / 64+tx*4) for conflict-free LDS.128 fragment loads.
// M implied by gridDim.y*128; M,N,K all multiples of tile sizes here.
// ---------------------------------------------------------------------------
__device__ __forceinline__ void gemm_body(const float* __restrict__ A,
                                          const float* __restrict__ B,
                                          const float* __restrict__ bias,
                                          float* __restrict__ C,
                                          const int K, const int N)
{
    __shared__ float As[16][128];
    __shared__ float Bs[16][128];

    const int tid  = threadIdx.x;
    const int brow = blockIdx.y * 128;
    const int bcol = blockIdx.x * 128;

    const int aRow = tid >> 2;          // 0..63 (and +64)
    const int aCol = (tid & 3) << 2;    // 0,4,8,12
    const int bRow = tid >> 5;          // 0..7 (and +8)
    const int bCol = (tid & 31) << 2;   // 0..124

    const int tx = tid & 15;
    const int ty = tid >> 4;

    float acc[8][8];
#pragma unroll
    for (int i = 0; i < 8; i++)
#pragma unroll
        for (int j = 0; j < 8; j++) acc[i][j] = 0.f;

    const float* Aptr0 = A + (size_t)(brow + aRow)      * K + aCol;
    const float* Aptr1 = A + (size_t)(brow + aRow + 64) * K + aCol;
    const float* Bptr0 = B + (size_t)bRow       * N + bcol + bCol;
    const float* Bptr1 = B + (size_t)(bRow + 8) * N + bcol + bCol;

    for (int k0 = 0; k0 < K; k0 += 16) {
        float4 a0 = *(const float4*)(Aptr0 + k0);
        float4 a1 = *(const float4*)(Aptr1 + k0);
        float4 b0 = *(const float4*)(Bptr0 + (size_t)k0 * N);
        float4 b1 = *(const float4*)(Bptr1 + (size_t)k0 * N);

        As[aCol + 0][aRow] = a0.x; As[aCol + 1][aRow] = a0.y;
        As[aCol + 2][aRow] = a0.z; As[aCol + 3][aRow] = a0.w;
        As[aCol + 0][aRow + 64] = a1.x; As[aCol + 1][aRow + 64] = a1.y;
        As[aCol + 2][aRow + 64] = a1.z; As[aCol + 3][aRow + 64] = a1.w;
        *(float4*)&Bs[bRow][bCol]     = b0;
        *(float4*)&Bs[bRow + 8][bCol] = b1;
        __syncthreads();

#pragma unroll
        for (int kk = 0; kk < 16; kk++) {
            float a[8], bf[8];
            *(float4*)&a[0]  = *(const float4*)&As[kk][ty * 4];
            *(float4*)&a[4]  = *(const float4*)&As[kk][64 + ty * 4];
            *(float4*)&bf[0] = *(const float4*)&Bs[kk][tx * 4];
            *(float4*)&bf[4] = *(const float4*)&Bs[kk][64 + tx * 4];
#pragma unroll
            for (int i = 0; i < 8; i++)
#pragma unroll
                for (int j = 0; j < 8; j++)
                    acc[i][j] = fmaf(a[i], bf[j], acc[i][j]);
        }
        __syncthreads();
    }

#pragma unroll
    for (int ih = 0; ih < 2; ih++)
#pragma unroll
        for (int i = 0; i < 4; i++) {
            const int r = brow + ih * 64 + ty * 4 + i;
#pragma unroll
            for (int jh = 0; jh < 2; jh++) {
                const int c = bcol + jh * 64 + tx * 4;
                float4 v;
                v.x = acc[ih * 4 + i][jh * 4 + 0];
                v.y = acc[ih * 4 + i][jh * 4 + 1];
                v.z = acc[ih * 4 + i][jh * 4 + 2];
                v.w = acc[ih * 4 + i][jh * 4 + 3];
                if (bias) {
                    v.x += bias[c + 0]; v.y += bias[c + 1];
                    v.z += bias[c + 2]; v.w += bias[c + 3];
                }
                *(float4*)&C[(size_t)r * N + c] = v;
            }
        }
}

// One launch computes Q, K and V projections (blockIdx.z selects weight/output)
__global__ __launch_bounds__(256) void qkv_gemm_kernel(const float* __restrict__ A,
                                                       const float* __restrict__ Wq,
                                                       const float* __restrict__ Wk,
                                                       const float* __restrict__ Wv)
{
    const float* B = (blockIdx.z == 0) ? Wq : (blockIdx.z == 1) ? Wk : Wv;
    float* C = (blockIdx.z == 0) ? g_q : (blockIdx.z == 1) ? g_k : g_v;
    gemm_body(A, B, nullptr, C, D_MODEL, D_MODEL);
}

__global__ __launch_bounds__(256) void out_gemm_kernel(const float* __restrict__ Wo,
                                                       const float* __restrict__ bo,
                                                       float* __restrict__ C)
{
    gemm_body(g_ctx, Wo, bo, C, D_MODEL, D_MODEL);
}

// ---------------------------------------------------------------------------
// Flash attention: per block = one (bh, 64-query tile). Streams 64 kv tiles of
// 32 (1024 own kv + 1024 alpha-scaled background kv). Online softmax; output
// written directly in batch-to-head [B, L, D] layout to g_ctx.
// ---------------------------------------------------------------------------
__global__ __launch_bounds__(256) void attn_kernel(const float* __restrict__ Kbg,
                                                   const float* __restrict__ Vbg)
{
    __shared__ float Qs[64][68];
    __shared__ float Ks[32][68];
    __shared__ float Vs[32][68];
    __shared__ float Ss[64][33];
    __shared__ float sc_s[64];
    __shared__ float linv_s[64];

    const int tid = threadIdx.x;
    const int bh  = blockIdx.y;
    const int b   = bh / NHEAD;
    const int h   = bh - b * NHEAD;
    const int q0  = blockIdx.x * 64;

    // Load Q tile (scale folded in): 64x64 floats, 4 float4 per thread
    const float* qbase = g_q + (size_t)(b * SEQ + q0) * D_MODEL + h * DHEAD;
#pragma unroll
    for (int p = 0; p < 4; p++) {
        const int idx = tid + 256 * p;
        const int r = idx >> 4;
        const int c = (idx & 15) << 2;
        float4 v = *(const float4*)(qbase + (size_t)r * D_MODEL + c);
        Qs[r][c + 0] = v.x * SM_SCALE; Qs[r][c + 1] = v.y * SM_SCALE;
        Qs[r][c + 2] = v.z * SM_SCALE; Qs[r][c + 3] = v.w * SM_SCALE;
    }

    float o0[8], o1[8];
#pragma unroll
    for (int i = 0; i < 8; i++) { o0[i] = 0.f; o1[i] = 0.f; }
    float m_reg = -1e30f, l_reg = 0.f;

    // PV / output mapping: rows pr and pr+32; cols pc..pc+3 and pc+32..pc+35
    const int pr = tid >> 3;
    const int pc = (tid & 7) << 2;
    // S mapping: cols sx and sx+16; rows sy..sy+3
    const int sx = tid & 15;
    const int sy = (tid >> 4) << 2;

    for (int it = 0; it < (2 * SEQ) / 32; it++) {
        const int j0 = it * 32;
        __syncthreads();   // Q tile ready (it=0); K/V/S consumers done (it>0)

        // Load K/V tile (32x64), 2 float4 per thread per tensor
#pragma unroll
        for (int p = 0; p < 2; p++) {
            const int idx = tid + 256 * p;
            const int r = idx >> 4;
            const int c = (idx & 15) << 2;
            float4 kv, vv;
            if (j0 < SEQ) {
                const size_t off = (size_t)(b * SEQ + j0 + r) * D_MODEL + h * DHEAD + c;
                kv = *(const float4*)(g_k + off);
                vv = *(const float4*)(g_v + off);
            } else {
                const size_t off = ((size_t)bh * SEQ + (j0 - SEQ + r)) * DHEAD + c;
                float4 t1 = *(const float4*)(Kbg + off);
                float4 t2 = *(const float4*)(Vbg + off);
                kv.x = t1.x * ALPHA_C; kv.y = t1.y * ALPHA_C;
                kv.z = t1.z * ALPHA_C; kv.w = t1.w * ALPHA_C;
                vv.x = t2.x * ALPHA_C; vv.y = t2.y * ALPHA_C;
                vv.z = t2.z * ALPHA_C; vv.w = t2.w * ALPHA_C;
            }
            *(float4*)&Ks[r][c] = kv;
            *(float4*)&Vs[r][c] = vv;
        }
        __syncthreads();

        // S = Q K^T  (4 rows x 2 cols per thread, float4 over dh)
        {
            float s0[4] = {0.f, 0.f, 0.f, 0.f};
            float s1[4] = {0.f, 0.f, 0.f, 0.f};
#pragma unroll
            for (int d = 0; d < DHEAD; d += 4) {
                float4 k0 = *(const float4*)&Ks[sx][d];
                float4 k1 = *(const float4*)&Ks[sx + 16][d];
#pragma unroll
                for (int i = 0; i < 4; i++) {
                    float4 qv = *(const float4*)&Qs[sy + i][d];
                    s0[i] = fmaf(qv.x, k0.x, fmaf(qv.y, k0.y,
                             fmaf(qv.z, k0.z, fmaf(qv.w, k0.w, s0[i]))));
                    s1[i] = fmaf(qv.x, k1.x, fmaf(qv.y, k1.y,
                             fmaf(qv.z, k1.z, fmaf(qv.w, k1.w, s1[i]))));
                }
            }
#pragma unroll
            for (int i = 0; i < 4; i++) {
                Ss[sy + i][sx]      = s0[i];
                Ss[sy + i][sx + 16] = s1[i];
            }
        }
        __syncthreads();

        // Online softmax: one thread per q row (threads 0..63)
        if (tid < 64) {
            float mx = m_reg;
#pragma unroll
            for (int j = 0; j < 32; j++) mx = fmaxf(mx, Ss[tid][j]);
            const float sc = __expf(m_reg - mx);
            float sum = 0.f;
#pragma unroll
            for (int j = 0; j < 32; j++) {
                const float pv = __expf(Ss[tid][j] - mx);
                Ss[tid][j] = pv;
                sum += pv;
            }
            l_reg = l_reg * sc + sum;
            m_reg = mx;
            sc_s[tid] = sc;
        }
        __syncthreads();

        // O = O*sc + P @ V
        {
            const float sca = sc_s[pr];
            const float scb = sc_s[pr + 32];
#pragma unroll
            for (int i = 0; i < 8; i++) { o0[i] *= sca; o1[i] *= scb; }
#pragma unroll
            for (int j = 0; j < 32; j++) {
                const float p0 = Ss[pr][j];
                const float p1 = Ss[pr + 32][j];
                float4 v0 = *(const float4*)&Vs[j][pc];
                float4 v1 = *(const float4*)&Vs[j][pc + 32];
                o0[0] = fmaf(p0, v0.x, o0[0]); o0[1] = fmaf(p0, v0.y, o0[1]);
                o0[2] = fmaf(p0, v0.z, o0[2]); o0[3] = fmaf(p0, v0.w, o0[3]);
                o0[4] = fmaf(p0, v1.x, o0[4]); o0[5] = fmaf(p0, v1.y, o0[5]);
                o0[6] = fmaf(p0, v1.z, o0[6]); o0[7] = fmaf(p0, v1.w, o0[7]);
                o1[0] = fmaf(p1, v0.x, o1[0]); o1[1] = fmaf(p1, v0.y, o1[1]);
                o1[2] = fmaf(p1, v0.z, o1[2]); o1[3] = fmaf(p1, v0.w, o1[3]);
                o1[4] = fmaf(p1, v1.x, o1[4]); o1[5] = fmaf(p1, v1.y, o1[5]);
                o1[6] = fmaf(p1, v1.z, o1[6]); o1[7] = fmaf(p1, v1.w, o1[7]);
            }
        }
    }

    if (tid < 64) linv_s[tid] = 1.0f / l_reg;
    __syncthreads();

    {
        const float li0 = linv_s[pr];
        const float li1 = linv_s[pr + 32];
        float* cbase = g_ctx + (size_t)(b * SEQ + q0) * D_MODEL + h * DHEAD;
        float4 w;
        w.x = o0[0] * li0; w.y = o0[1] * li0; w.z = o0[2] * li0; w.w = o0[3] * li0;
        *(float4*)&cbase[(size_t)pr * D_MODEL + pc] = w;
        w.x = o0[4] * li0; w.y = o0[5] * li0; w.z = o0[6] * li0; w.w = o0[7] * li0;
        *(float4*)&cbase[(size_t)pr * D_MODEL + pc + 32] = w;
        w.x = o1[0] * li1; w.y = o1[1] * li1; w.z = o1[2] * li1; w.w = o1[3] * li1;
        *(float4*)&cbase[(size_t)(pr + 32) * D_MODEL + pc] = w;
        w.x = o1[4] * li1; w.y = o1[5] * li1; w.z = o1[6] * li1; w.w = o1[7] * li1;
        *(float4*)&cbase[(size_t)(pr + 32) * D_MODEL + pc + 32] = w;
    }
}

// ---------------------------------------------------------------------------
extern "C" void kernel_launch(void* const* d_in, const int* in_sizes, int n_in,
                              void* d_out, int out_size)
{
    const float* hs  = (const float*)d_in[0];
    const float* Wq  = (const float*)d_in[1];
    const float* Wk  = (const float*)d_in[2];
    const float* Wv  = (const float*)d_in[3];
    const float* Wo  = (const float*)d_in[4];
    const float* bo  = (const float*)d_in[5];
    const float* Kbg = (const float*)d_in[6];
    const float* Vbg = (const float*)d_in[7];
    float* out = (float*)d_out;

    // 1) Q/K/V projections: one batched launch
    dim3 gqkv(D_MODEL / 128, M_TOTAL / 128, 3);
    qkv_gemm_kernel<<<gqkv, 256>>>(hs, Wq, Wk, Wv);

    // 2) Attention with injected background K/V
    dim3 gattn(SEQ / 64, BHEADS);
    attn_kernel<<<gattn, 256>>>(Kbg, Vbg);

    // 3) Output projection + bias
    dim3 gout(D_MODEL / 128, M_TOTAL / 128);
    out_gemm_kernel<<<gout, 256>>>(Wo, bo, out);
}

// round 4
// speedup vs baseline: 1.0322x; 1.0322x over previous
#include <cuda_runtime.h>
#include <math.h>

// Problem constants (fixed shapes from reference)
#define D_MODEL 1280
#define NHEAD   20
#define DHEAD   64
#define BATCH   4
#define SEQ     1024
#define BHEADS  (BATCH*NHEAD)      // 80
#define M_TOTAL (BATCH*SEQ)        // 4096
#define ALPHA_C 0.48f
#define SM_SCALE 0.125f            // 1/sqrt(64)

typedef unsigned long long u64;

// ---- packed f32x2 helpers (FFMA2 only reachable via PTX) ----
__device__ __forceinline__ u64 splat2(float x) {
    u64 r; asm("mov.b64 %0,{%1,%1};" : "=l"(r) : "f"(x)); return r;
}
__device__ __forceinline__ u64 pk2(float a, float b) {
    u64 r; asm("mov.b64 %0,{%1,%2};" : "=l"(r) : "f"(a), "f"(b)); return r;
}
__device__ __forceinline__ void fma2(u64& d, u64 a, u64 b) {
    asm("fma.rn.f32x2 %0,%1,%2,%0;" : "+l"(d) : "l"(a), "l"(b));
}
__device__ __forceinline__ u64 mul2(u64 a, u64 b) {
    u64 r; asm("mul.rn.f32x2 %0,%1,%2;" : "=l"(r) : "l"(a), "l"(b)); return r;
}
__device__ __forceinline__ float2 up2(u64 v) {
    float2 f; asm("mov.b64 {%0,%1},%2;" : "=f"(f.x), "=f"(f.y) : "l"(v)); return f;
}

// Scratch (device globals: no allocation allowed in kernel_launch)
__device__ float g_q[M_TOTAL * D_MODEL];
__device__ float g_k[M_TOTAL * D_MODEL];
__device__ float g_v[M_TOTAL * D_MODEL];
__device__ float g_ctx[M_TOTAL * D_MODEL];

// ---------------------------------------------------------------------------
// SGEMM: C[M,N] = A[M,K] @ B[K,N] (+ bias). 128x128 tile, BK=16, 256 threads,
// 8x8 microtile, inner product done with packed fma.rn.f32x2 (2 cols/op).
// ---------------------------------------------------------------------------
__device__ __forceinline__ void gemm_body(const float* __restrict__ A,
                                          const float* __restrict__ B,
                                          const float* __restrict__ bias,
                                          float* __restrict__ C,
                                          const int K, const int N)
{
    __shared__ float As[16][128];
    __shared__ float Bs[16][128];

    const int tid  = threadIdx.x;
    const int brow = blockIdx.y * 128;
    const int bcol = blockIdx.x * 128;

    const int aRow = tid >> 2;          // 0..63 (and +64)
    const int aCol = (tid & 3) << 2;    // 0,4,8,12
    const int bRow = tid >> 5;          // 0..7 (and +8)
    const int bCol = (tid & 31) << 2;   // 0..124

    const int tx = tid & 15;
    const int ty = tid >> 4;

    u64 acc2[8][4];
#pragma unroll
    for (int i = 0; i < 8; i++)
#pragma unroll
        for (int j = 0; j < 4; j++) acc2[i][j] = 0ull;

    const float* Aptr0 = A + (size_t)(brow + aRow)      * K + aCol;
    const float* Aptr1 = A + (size_t)(brow + aRow + 64) * K + aCol;
    const float* Bptr0 = B + (size_t)bRow       * N + bcol + bCol;
    const float* Bptr1 = B + (size_t)(bRow + 8) * N + bcol + bCol;

    for (int k0 = 0; k0 < K; k0 += 16) {
        float4 a0 = *(const float4*)(Aptr0 + k0);
        float4 a1 = *(const float4*)(Aptr1 + k0);
        float4 b0 = *(const float4*)(Bptr0 + (size_t)k0 * N);
        float4 b1 = *(const float4*)(Bptr1 + (size_t)k0 * N);

        As[aCol + 0][aRow] = a0.x; As[aCol + 1][aRow] = a0.y;
        As[aCol + 2][aRow] = a0.z; As[aCol + 3][aRow] = a0.w;
        As[aCol + 0][aRow + 64] = a1.x; As[aCol + 1][aRow + 64] = a1.y;
        As[aCol + 2][aRow + 64] = a1.z; As[aCol + 3][aRow + 64] = a1.w;
        *(float4*)&Bs[bRow][bCol]     = b0;
        *(float4*)&Bs[bRow + 8][bCol] = b1;
        __syncthreads();

#pragma unroll
        for (int kk = 0; kk < 16; kk++) {
            float a[8];
            *(float4*)&a[0] = *(const float4*)&As[kk][ty * 4];
            *(float4*)&a[4] = *(const float4*)&As[kk][64 + ty * 4];
            float4 bA = *(const float4*)&Bs[kk][tx * 4];
            float4 bB = *(const float4*)&Bs[kk][64 + tx * 4];
            u64 b2[4];
            b2[0] = pk2(bA.x, bA.y); b2[1] = pk2(bA.z, bA.w);
            b2[2] = pk2(bB.x, bB.y); b2[3] = pk2(bB.z, bB.w);
#pragma unroll
            for (int i = 0; i < 8; i++) {
                u64 as = splat2(a[i]);
                fma2(acc2[i][0], as, b2[0]);
                fma2(acc2[i][1], as, b2[1]);
                fma2(acc2[i][2], as, b2[2]);
                fma2(acc2[i][3], as, b2[3]);
            }
        }
        __syncthreads();
    }

#pragma unroll
    for (int ih = 0; ih < 2; ih++)
#pragma unroll
        for (int i = 0; i < 4; i++) {
            const int r = brow + ih * 64 + ty * 4 + i;
            const int idx = ih * 4 + i;
#pragma unroll
            for (int jh = 0; jh < 2; jh++) {
                const int c = bcol + jh * 64 + tx * 4;
                float2 x0 = up2(acc2[idx][jh * 2 + 0]);
                float2 x1 = up2(acc2[idx][jh * 2 + 1]);
                float4 v; v.x = x0.x; v.y = x0.y; v.z = x1.x; v.w = x1.y;
                if (bias) {
                    v.x += bias[c + 0]; v.y += bias[c + 1];
                    v.z += bias[c + 2]; v.w += bias[c + 3];
                }
                *(float4*)&C[(size_t)r * N + c] = v;
            }
        }
}

// One launch computes Q, K and V projections (blockIdx.z selects weight/output)
__global__ __launch_bounds__(256) void qkv_gemm_kernel(const float* __restrict__ A,
                                                       const float* __restrict__ Wq,
                                                       const float* __restrict__ Wk,
                                                       const float* __restrict__ Wv)
{
    const float* B = (blockIdx.z == 0) ? Wq : (blockIdx.z == 1) ? Wk : Wv;
    float* C = (blockIdx.z == 0) ? g_q : (blockIdx.z == 1) ? g_k : g_v;
    gemm_body(A, B, nullptr, C, D_MODEL, D_MODEL);
}

__global__ __launch_bounds__(256) void out_gemm_kernel(const float* __restrict__ Wo,
                                                       const float* __restrict__ bo,
                                                       float* __restrict__ C)
{
    gemm_body(g_ctx, Wo, bo, C, D_MODEL, D_MODEL);
}

// ---------------------------------------------------------------------------
// Flash attention: per block = one (bh, 64-query tile). Streams 64 kv tiles of
// 32 (1024 own kv + 1024 alpha-scaled background kv). Online softmax (all 256
// threads, shfl-reduced). f32x2 packed math in QK^T and PV. Output written in
// batch-to-head [B, L, D] layout to g_ctx.
// ---------------------------------------------------------------------------
#define QKV_STRIDE 66   // conflict-free for u64 (LDS.64) column reads

__global__ __launch_bounds__(256) void attn_kernel(const float* __restrict__ Kbg,
                                                   const float* __restrict__ Vbg)
{
    __shared__ float Qs[64][QKV_STRIDE];
    __shared__ float Ks[32][QKV_STRIDE];
    __shared__ float Vs[32][QKV_STRIDE];
    __shared__ float Ss[64][33];
    __shared__ float sc_s[64];
    __shared__ float m_s[64];
    __shared__ float l_s[64];

    const int tid = threadIdx.x;
    const int bh  = blockIdx.y;
    const int b   = bh / NHEAD;
    const int h   = bh - b * NHEAD;
    const int q0  = blockIdx.x * 64;

    // Load Q tile (scale folded in): 64x64 floats
    const float* qbase = g_q + (size_t)(b * SEQ + q0) * D_MODEL + h * DHEAD;
#pragma unroll
    for (int p = 0; p < 4; p++) {
        const int idx = tid + 256 * p;
        const int r = idx >> 4;
        const int c = (idx & 15) << 2;
        float4 v = *(const float4*)(qbase + (size_t)r * D_MODEL + c);
        *(u64*)&Qs[r][c + 0] = pk2(v.x * SM_SCALE, v.y * SM_SCALE);
        *(u64*)&Qs[r][c + 2] = pk2(v.z * SM_SCALE, v.w * SM_SCALE);
    }
    if (tid < 64) { m_s[tid] = -1e30f; l_s[tid] = 0.f; }

    u64 O0[4], O1[4];
#pragma unroll
    for (int i = 0; i < 4; i++) { O0[i] = 0ull; O1[i] = 0ull; }

    // PV / output mapping: rows pr and pr+32; col pairs at pc, pc+2, pc+32, pc+34
    const int pr = tid >> 3;
    const int pc = (tid & 7) << 2;
    // S mapping (QK): cols sx and sx+16; rows sy..sy+3
    const int sx = tid & 15;
    const int sy = (tid >> 4) << 2;
    // softmax mapping: row rt, quarter qd (8 cols each)
    const int rt = tid >> 2;
    const int qd = tid & 3;

    for (int it = 0; it < (2 * SEQ) / 32; it++) {
        const int j0 = it * 32;
        __syncthreads();   // Q/m/l ready (it=0); K/V/S consumers done (it>0)

        // Load K/V tile (32x64)
#pragma unroll
        for (int p = 0; p < 2; p++) {
            const int idx = tid + 256 * p;
            const int r = idx >> 4;
            const int c = (idx & 15) << 2;
            float4 kv, vv;
            if (j0 < SEQ) {
                const size_t off = (size_t)(b * SEQ + j0 + r) * D_MODEL + h * DHEAD + c;
                kv = *(const float4*)(g_k + off);
                vv = *(const float4*)(g_v + off);
            } else {
                const size_t off = ((size_t)bh * SEQ + (j0 - SEQ + r)) * DHEAD + c;
                float4 t1 = *(const float4*)(Kbg + off);
                float4 t2 = *(const float4*)(Vbg + off);
                kv.x = t1.x * ALPHA_C; kv.y = t1.y * ALPHA_C;
                kv.z = t1.z * ALPHA_C; kv.w = t1.w * ALPHA_C;
                vv.x = t2.x * ALPHA_C; vv.y = t2.y * ALPHA_C;
                vv.z = t2.z * ALPHA_C; vv.w = t2.w * ALPHA_C;
            }
            *(u64*)&Ks[r][c + 0] = pk2(kv.x, kv.y);
            *(u64*)&Ks[r][c + 2] = pk2(kv.z, kv.w);
            *(u64*)&Vs[r][c + 0] = pk2(vv.x, vv.y);
            *(u64*)&Vs[r][c + 2] = pk2(vv.z, vv.w);
        }
        __syncthreads();

        // S = Q K^T  (4 rows x 2 cols per thread, packed over dh)
        {
            u64 s0[4] = {0ull, 0ull, 0ull, 0ull};
            u64 s1[4] = {0ull, 0ull, 0ull, 0ull};
#pragma unroll
            for (int d = 0; d < DHEAD; d += 2) {
                u64 k0 = *(const u64*)&Ks[sx][d];
                u64 k1 = *(const u64*)&Ks[sx + 16][d];
#pragma unroll
                for (int i = 0; i < 4; i++) {
                    u64 q2 = *(const u64*)&Qs[sy + i][d];
                    fma2(s0[i], q2, k0);
                    fma2(s1[i], q2, k1);
                }
            }
#pragma unroll
            for (int i = 0; i < 4; i++) {
                float2 a = up2(s0[i]);
                float2 c = up2(s1[i]);
                Ss[sy + i][sx]      = a.x + a.y;
                Ss[sy + i][sx + 16] = c.x + c.y;
            }
        }
        __syncthreads();

        // Online softmax: 4 lanes per row, 8 cols per lane, shfl reductions
        {
            float vals[8];
#pragma unroll
            for (int j = 0; j < 8; j++) vals[j] = Ss[rt][qd * 8 + j];
            float mx = vals[0];
#pragma unroll
            for (int j = 1; j < 8; j++) mx = fmaxf(mx, vals[j]);
            mx = fmaxf(mx, __shfl_xor_sync(0xFFFFFFFFu, mx, 1));
            mx = fmaxf(mx, __shfl_xor_sync(0xFFFFFFFFu, mx, 2));
            const float m_old = m_s[rt];
            mx = fmaxf(mx, m_old);
            float sum = 0.f;
#pragma unroll
            for (int j = 0; j < 8; j++) {
                const float pv = __expf(vals[j] - mx);
                Ss[rt][qd * 8 + j] = pv;
                sum += pv;
            }
            sum += __shfl_xor_sync(0xFFFFFFFFu, sum, 1);
            sum += __shfl_xor_sync(0xFFFFFFFFu, sum, 2);
            if (qd == 0) {
                const float sc = __expf(m_old - mx);
                l_s[rt] = l_s[rt] * sc + sum;
                m_s[rt] = mx;
                sc_s[rt] = sc;
            }
        }
        __syncthreads();

        // O = O*sc + P @ V   (packed pairs of output columns)
        {
            const u64 sa = splat2(sc_s[pr]);
            const u64 sb = splat2(sc_s[pr + 32]);
#pragma unroll
            for (int i = 0; i < 4; i++) { O0[i] = mul2(O0[i], sa); O1[i] = mul2(O1[i], sb); }
#pragma unroll
            for (int j = 0; j < 32; j++) {
                const u64 p0 = splat2(Ss[pr][j]);
                const u64 p1 = splat2(Ss[pr + 32][j]);
                const u64 v0 = *(const u64*)&Vs[j][pc + 0];
                const u64 v1 = *(const u64*)&Vs[j][pc + 2];
                const u64 v2 = *(const u64*)&Vs[j][pc + 32];
                const u64 v3 = *(const u64*)&Vs[j][pc + 34];
                fma2(O0[0], p0, v0); fma2(O0[1], p0, v1);
                fma2(O0[2], p0, v2); fma2(O0[3], p0, v3);
                fma2(O1[0], p1, v0); fma2(O1[1], p1, v1);
                fma2(O1[2], p1, v2); fma2(O1[3], p1, v3);
            }
        }
    }

    // Normalize and store (batch-to-head [B, L, D] layout)
    {
        const u64 li0 = splat2(1.0f / l_s[pr]);
        const u64 li1 = splat2(1.0f / l_s[pr + 32]);
        float* cbase = g_ctx + (size_t)(b * SEQ + q0) * D_MODEL + h * DHEAD;
        float2 a0 = up2(mul2(O0[0], li0));
        float2 a1 = up2(mul2(O0[1], li0));
        float2 a2 = up2(mul2(O0[2], li0));
        float2 a3 = up2(mul2(O0[3], li0));
        float4 w;
        w.x = a0.x; w.y = a0.y; w.z = a1.x; w.w = a1.y;
        *(float4*)&cbase[(size_t)pr * D_MODEL + pc] = w;
        w.x = a2.x; w.y = a2.y; w.z = a3.x; w.w = a3.y;
        *(float4*)&cbase[(size_t)pr * D_MODEL + pc + 32] = w;
        a0 = up2(mul2(O1[0], li1));
        a1 = up2(mul2(O1[1], li1));
        a2 = up2(mul2(O1[2], li1));
        a3 = up2(mul2(O1[3], li1));
        w.x = a0.x; w.y = a0.y; w.z = a1.x; w.w = a1.y;
        *(float4*)&cbase[(size_t)(pr + 32) * D_MODEL + pc] = w;
        w.x = a2.x; w.y = a2.y; w.z = a3.x; w.w = a3.y;
        *(float4*)&cbase[(size_t)(pr + 32) * D_MODEL + pc + 32] = w;
    }
}

// ---------------------------------------------------------------------------
extern "C" void kernel_launch(void* const* d_in, const int* in_sizes, int n_in,
                              void* d_out, int out_size)
{
    const float* hs  = (const float*)d_in[0];
    const float* Wq  = (const float*)d_in[1];
    const float* Wk  = (const float*)d_in[2];
    const float* Wv  = (const float*)d_in[3];
    const float* Wo  = (const float*)d_in[4];
    const float* bo  = (const float*)d_in[5];
    const float* Kbg = (const float*)d_in[6];
    const float* Vbg = (const float*)d_in[7];
    float* out = (float*)d_out;

    // 1) Q/K/V projections: one batched launch
    dim3 gqkv(D_MODEL / 128, M_TOTAL / 128, 3);
    qkv_gemm_kernel<<<gqkv, 256>>>(hs, Wq, Wk, Wv);

    // 2) Attention with injected background K/V
    dim3 gattn(SEQ / 64, BHEADS);
    attn_kernel<<<gattn, 256>>>(Kbg, Vbg);

    // 3) Output projection + bias
    dim3 gout(D_MODEL / 128, M_TOTAL / 128);
    out_gemm_kernel<<<gout, 256>>>(Wo, bo, out);
}

// round 12
// speedup vs baseline: 3.9328x; 3.8103x over previous
#include <cuda_runtime.h>
#include <cuda_fp16.h>
#include <cstdint>
#include <math.h>

// Problem constants
#define D_MODEL 1280
#define NHEAD   20
#define DHEAD   64
#define BATCH   4
#define SEQ     1024
#define BHEADS  (BATCH*NHEAD)      // 80
#define M_TOTAL (BATCH*SEQ)        // 4096
#define ALPHA_C 0.48f
#define SM_SCALE 0.125f

typedef uint32_t u32;

// ---------------- scratch (device globals; referenced ONLY from device code) --
__device__ __align__(16) __half g_xh[M_TOTAL * D_MODEL];   // hs fp16
__device__ __align__(16) __half g_qh[M_TOTAL * D_MODEL];   // Q * SM_SCALE, fp16
__device__ __align__(16) __half g_kh[M_TOTAL * D_MODEL];
__device__ __align__(16) __half g_vh[M_TOTAL * D_MODEL];
__device__ __align__(16) __half g_ah[M_TOTAL * D_MODEL];   // attention output fp16
__device__ __align__(16) __half g_wt[4 * D_MODEL * D_MODEL]; // W^T fp16, [w][n*K+k]

// ---------------- helpers ----------------
__device__ __forceinline__ u32 smem_u32(const void* p) {
    u32 a;
    asm("{ .reg .u64 t; cvta.to.shared.u64 t, %1; cvt.u32.u64 %0, t; }"
        : "=r"(a) : "l"(p));
    return a;
}
__device__ __forceinline__ u32 pkh2(float lo, float hi) {
    __half2 h = __floats2half2_rn(lo, hi);
    return *(u32*)&h;
}
__device__ __forceinline__ void ldm_x4(u32 addr, u32 r[4]) {
    asm volatile("ldmatrix.sync.aligned.m8n8.x4.shared.b16 {%0,%1,%2,%3}, [%4];"
                 : "=r"(r[0]), "=r"(r[1]), "=r"(r[2]), "=r"(r[3]) : "r"(addr));
}
__device__ __forceinline__ void ldm_x4_t(u32 addr, u32 r[4]) {
    asm volatile("ldmatrix.sync.aligned.m8n8.x4.trans.shared.b16 {%0,%1,%2,%3}, [%4];"
                 : "=r"(r[0]), "=r"(r[1]), "=r"(r[2]), "=r"(r[3]) : "r"(addr));
}
__device__ __forceinline__ void mma16816(float d[4], const u32 a[4], u32 b0, u32 b1) {
    asm volatile(
        "mma.sync.aligned.m16n8k16.row.col.f32.f16.f16.f32 "
        "{%0,%1,%2,%3},{%4,%5,%6,%7},{%8,%9},{%0,%1,%2,%3};"
        : "+f"(d[0]), "+f"(d[1]), "+f"(d[2]), "+f"(d[3])
        : "r"(a[0]), "r"(a[1]), "r"(a[2]), "r"(a[3]), "r"(b0), "r"(b1));
}

// ---------------- prep kernels ----------------
// fp32 -> fp16 conversion of hidden_states into g_xh (dst fixed inside device code)
__global__ __launch_bounds__(256) void conv_kernel(const float* __restrict__ src)
{
    const int i = (blockIdx.x * 256 + threadIdx.x) * 8;
    float4 a = *(const float4*)(src + i);
    float4 b = *(const float4*)(src + i + 4);
    uint4 o;
    o.x = pkh2(a.x, a.y); o.y = pkh2(a.z, a.w);
    o.z = pkh2(b.x, b.y); o.w = pkh2(b.z, b.w);
    *(uint4*)(g_xh + i) = o;
}

// Transpose W [K,N] -> W^T [N,K] fp16
__global__ __launch_bounds__(256) void prep_w_kernel(const float* __restrict__ Wq,
                                                     const float* __restrict__ Wk,
                                                     const float* __restrict__ Wv,
                                                     const float* __restrict__ Wo)
{
    const int w = blockIdx.z;
    const float* W = (w == 0) ? Wq : (w == 1) ? Wk : (w == 2) ? Wv : Wo;
    __half* dst = g_wt + (size_t)w * D_MODEL * D_MODEL;

    __shared__ float t[32][33];
    const int tx = threadIdx.x & 31, ty = threadIdx.x >> 5;   // 32x8
    const int n0 = blockIdx.x * 32, k0 = blockIdx.y * 32;
#pragma unroll
    for (int i = 0; i < 4; i++)
        t[ty + i * 8][tx] = W[(size_t)(k0 + ty + i * 8) * D_MODEL + n0 + tx];
    __syncthreads();
#pragma unroll
    for (int i = 0; i < 4; i++)
        dst[(size_t)(n0 + ty + i * 8) * D_MODEL + k0 + tx] =
            __float2half_rn(t[tx][ty + i * 8]);
}

// ---------------- fp16 mma.sync GEMM ----------------
// C[128x128 tile] = A[M,1280] @ W^T[n][k]. 8 warps: 4(m) x 2(n), warp 32x64.
#define AST 40
#define BST 40

__device__ __forceinline__ void mm_body(const __half* __restrict__ A,
                                        const __half* __restrict__ Bt,
                                        __half* __restrict__ Ch,
                                        float* __restrict__ Cf,
                                        const float* __restrict__ bias,
                                        const float scale)
{
    __shared__ __align__(16) __half As[128 * AST];
    __shared__ __align__(16) __half Bs[128 * BST];

    const int tid  = threadIdx.x;
    const int wid  = tid >> 5;
    const int lane = tid & 31;
    const int g    = lane >> 2;
    const int t4   = lane & 3;

    const int brow = blockIdx.y * 128;
    const int bcol = blockIdx.x * 128;

    const int wm = wid >> 1, wn = wid & 1;
    const int m0 = wm * 32, n0 = wn * 64;

    const u32 asb = smem_u32(As);
    const u32 bsb = smem_u32(Bs);

    const int lr = tid >> 1;
    const int lc = (tid & 1) * 16;
    const __half* Agp = A  + (size_t)(brow + lr) * D_MODEL + lc;
    const __half* Bgp = Bt + (size_t)(bcol + lr) * D_MODEL + lc;

    const u32 aAddr = asb + (u32)(((m0 + (lane & 15)) * AST + 8 * (lane >> 4)) * 2);
    const u32 bAddr = bsb + (u32)(((n0 + ((lane >> 4) << 3) + (lane & 7)) * BST
                                   + 8 * ((lane >> 3) & 1)) * 2);

    float acc[2][8][4];
#pragma unroll
    for (int i = 0; i < 2; i++)
#pragma unroll
        for (int j = 0; j < 8; j++)
#pragma unroll
            for (int q = 0; q < 4; q++) acc[i][j][q] = 0.f;

    for (int k0 = 0; k0 < D_MODEL; k0 += 32) {
        uint4 av0 = *(const uint4*)(Agp + k0);
        uint4 av1 = *(const uint4*)(Agp + k0 + 8);
        uint4 bv0 = *(const uint4*)(Bgp + k0);
        uint4 bv1 = *(const uint4*)(Bgp + k0 + 8);
        *(uint4*)&As[lr * AST + lc]     = av0;
        *(uint4*)&As[lr * AST + lc + 8] = av1;
        *(uint4*)&Bs[lr * BST + lc]     = bv0;
        *(uint4*)&Bs[lr * BST + lc + 8] = bv1;
        __syncthreads();

#pragma unroll
        for (int kk = 0; kk < 32; kk += 16) {
            u32 aF[2][4];
            ldm_x4(aAddr + kk * 2, aF[0]);
            ldm_x4(aAddr + (16 * AST + kk) * 2, aF[1]);
            u32 bF[4][4];
#pragma unroll
            for (int p = 0; p < 4; p++)
                ldm_x4(bAddr + (p * 16 * BST + kk) * 2, bF[p]);
#pragma unroll
            for (int mt = 0; mt < 2; mt++)
#pragma unroll
                for (int p = 0; p < 4; p++) {
                    mma16816(acc[mt][p * 2 + 0], aF[mt], bF[p][0], bF[p][1]);
                    mma16816(acc[mt][p * 2 + 1], aF[mt], bF[p][2], bF[p][3]);
                }
        }
        __syncthreads();
    }

#pragma unroll
    for (int mt = 0; mt < 2; mt++) {
        const int r0 = brow + m0 + mt * 16 + g;
#pragma unroll
        for (int nj = 0; nj < 8; nj++) {
            const int col = bcol + n0 + nj * 8 + 2 * t4;
            float* d = acc[mt][nj];
            if (Ch) {
                *(u32*)&Ch[(size_t)r0 * D_MODEL + col] = pkh2(d[0] * scale, d[1] * scale);
                *(u32*)&Ch[(size_t)(r0 + 8) * D_MODEL + col] = pkh2(d[2] * scale, d[3] * scale);
            } else {
                float2 v;
                v.x = d[0] + bias[col]; v.y = d[1] + bias[col + 1];
                *(float2*)&Cf[(size_t)r0 * D_MODEL + col] = v;
                v.x = d[2] + bias[col]; v.y = d[3] + bias[col + 1];
                *(float2*)&Cf[(size_t)(r0 + 8) * D_MODEL + col] = v;
            }
        }
    }
}

__global__ __launch_bounds__(256) void qkv_mm_kernel()
{
    const int z = blockIdx.z;
    __half* C = (z == 0) ? g_qh : (z == 1) ? g_kh : g_vh;
    mm_body(g_xh, g_wt + (size_t)z * D_MODEL * D_MODEL, C, nullptr, nullptr,
            (z == 0) ? SM_SCALE : 1.0f);
}

__global__ __launch_bounds__(256) void out_mm_kernel(const float* __restrict__ bo,
                                                     float* __restrict__ out)
{
    mm_body(g_ah, g_wt + (size_t)3 * D_MODEL * D_MODEL, nullptr, out, bo, 1.0f);
}

// ---------------- flash attention on mma.sync fp16 ----------------
// Block = (bh, 64-q tile), 256 threads = 8 warps: wm = wid>>1 (m16), wn = wid&1.
// QK^T: warp computes S[16 x 16] at rows 16*wm, cols 16*wn.
// PV:   warp computes O[16 x 32] at rows 16*wm, cols 32*wn.
#define QKS 72   // fp16 row stride for Qs/Ks/Vs
#define SST 34   // fp32 row stride for Ss
#define PST 40   // fp16 row stride for Ps

__global__ __launch_bounds__(256) void attn_kernel(const float* __restrict__ Kbg,
                                                   const float* __restrict__ Vbg)
{
    __shared__ __align__(16) __half Qs[64 * QKS];
    __shared__ __align__(16) __half Ks[32 * QKS];
    __shared__ __align__(16) __half Vs[32 * QKS];
    __shared__ __align__(16) float  Ss[64 * SST];
    __shared__ __align__(16) __half Ps[64 * PST];
    __shared__ float sc_s[64], m_s[64], l_s[64];

    const int tid  = threadIdx.x;
    const int wid  = tid >> 5;
    const int lane = tid & 31;
    const int g    = lane >> 2;
    const int t4   = lane & 3;

    const int bh = blockIdx.y;
    const int b  = bh / NHEAD;
    const int h  = bh - b * NHEAD;
    const int q0 = blockIdx.x * 64;

    const int wm = wid >> 1, wn = wid & 1;
    const int m0 = wm * 16;

    // ---- load Q tile (fp16, scale already folded by GEMM) ----
    {
        const __half* qg = g_qh + (size_t)(b * SEQ + q0) * D_MODEL + h * DHEAD;
        const int r = tid >> 2;
        const int c = (tid & 3) * 16;
        *(uint4*)&Qs[r * QKS + c]     = *(const uint4*)(qg + (size_t)r * D_MODEL + c);
        *(uint4*)&Qs[r * QKS + c + 8] = *(const uint4*)(qg + (size_t)r * D_MODEL + c + 8);
    }
    if (tid < 64) { m_s[tid] = -1e30f; l_s[tid] = 0.f; }
    __syncthreads();

    // ---- preload Q fragments (invariant across kv loop) ----
    u32 qa[4][4];
    {
        const u32 qsb = smem_u32(Qs);
        const u32 base = qsb + (u32)(((m0 + (lane & 15)) * QKS + 8 * (lane >> 4)) * 2);
#pragma unroll
        for (int kk = 0; kk < 4; kk++) ldm_x4(base + kk * 32, qa[kk]);
    }

    const u32 ksb = smem_u32(Ks);
    const u32 vsb = smem_u32(Vs);
    const u32 psb = smem_u32(Ps);
    // K B-frag addr (non-trans; Ks is [n=kv][k=dh], k-contiguous = col-major B)
    const u32 kAddr = ksb + (u32)(((wn * 16 + ((lane >> 4) << 3) + (lane & 7)) * QKS
                                   + 8 * ((lane >> 3) & 1)) * 2);
    // P A-frag addr
    const u32 pAddr = psb + (u32)(((m0 + (lane & 15)) * PST + 8 * (lane >> 4)) * 2);
    // V B-frag addr (trans; Vs is [k=kv][n=dh] row-major)
    const u32 vAddr = vsb + (u32)(((8 * ((lane >> 3) & 1) + (lane & 7)) * QKS
                                   + wn * 32 + 8 * (lane >> 4)) * 2);

    float oacc[4][4];
#pragma unroll
    for (int i = 0; i < 4; i++)
#pragma unroll
        for (int j = 0; j < 4; j++) oacc[i][j] = 0.f;

    const int rt = tid >> 2, qd = tid & 3;   // softmax mapping

    for (int it = 0; it < (2 * SEQ) / 32; it++) {
        const int j0 = it * 32;
        __syncthreads();   // protect Ks/Vs/Ps from previous consumers

        // ---- load K/V tile (32 x 64) ----
        {
            const int r = tid >> 3;
            const int c = (tid & 7) * 8;
            uint4 kv, vv;
            if (j0 < SEQ) {
                const size_t off = (size_t)(b * SEQ + j0 + r) * D_MODEL + h * DHEAD + c;
                kv = *(const uint4*)(g_kh + off);
                vv = *(const uint4*)(g_vh + off);
            } else {
                const size_t off = ((size_t)bh * SEQ + (j0 - SEQ + r)) * DHEAD + c;
                float4 a = *(const float4*)(Kbg + off);
                float4 d = *(const float4*)(Kbg + off + 4);
                kv.x = pkh2(a.x * ALPHA_C, a.y * ALPHA_C);
                kv.y = pkh2(a.z * ALPHA_C, a.w * ALPHA_C);
                kv.z = pkh2(d.x * ALPHA_C, d.y * ALPHA_C);
                kv.w = pkh2(d.z * ALPHA_C, d.w * ALPHA_C);
                a = *(const float4*)(Vbg + off);
                d = *(const float4*)(Vbg + off + 4);
                vv.x = pkh2(a.x * ALPHA_C, a.y * ALPHA_C);
                vv.y = pkh2(a.z * ALPHA_C, a.w * ALPHA_C);
                vv.z = pkh2(d.x * ALPHA_C, d.y * ALPHA_C);
                vv.w = pkh2(d.z * ALPHA_C, d.w * ALPHA_C);
            }
            *(uint4*)&Ks[r * QKS + c] = kv;
            *(uint4*)&Vs[r * QKS + c] = vv;
        }
        __syncthreads();

        // ---- S = Q K^T (warp: 16 rows x 16 cols) ----
        {
            float sd[2][4] = {{0.f, 0.f, 0.f, 0.f}, {0.f, 0.f, 0.f, 0.f}};
#pragma unroll
            for (int kk = 0; kk < 4; kk++) {
                u32 kb[4];
                ldm_x4(kAddr + kk * 32, kb);
                mma16816(sd[0], qa[kk], kb[0], kb[1]);
                mma16816(sd[1], qa[kk], kb[2], kb[3]);
            }
            const int row = m0 + g;
#pragma unroll
            for (int nt = 0; nt < 2; nt++) {
                const int col = wn * 16 + nt * 8 + 2 * t4;
                float2 v;
                v.x = sd[nt][0]; v.y = sd[nt][1];
                *(float2*)&Ss[row * SST + col] = v;
                v.x = sd[nt][2]; v.y = sd[nt][3];
                *(float2*)&Ss[(row + 8) * SST + col] = v;
            }
        }
        __syncthreads();

        // ---- online softmax (fp32), write P as fp16 ----
        {
            float vals[8];
#pragma unroll
            for (int j = 0; j < 8; j++) vals[j] = Ss[rt * SST + qd * 8 + j];
            float mx = vals[0];
#pragma unroll
            for (int j = 1; j < 8; j++) mx = fmaxf(mx, vals[j]);
            mx = fmaxf(mx, __shfl_xor_sync(0xFFFFFFFFu, mx, 1));
            mx = fmaxf(mx, __shfl_xor_sync(0xFFFFFFFFu, mx, 2));
            const float m_old = m_s[rt];
            mx = fmaxf(mx, m_old);
            float pv[8];
            float sum = 0.f;
#pragma unroll
            for (int j = 0; j < 8; j++) {
                pv[j] = __expf(vals[j] - mx);
                sum += pv[j];
            }
            uint4 pp;
            pp.x = pkh2(pv[0], pv[1]); pp.y = pkh2(pv[2], pv[3]);
            pp.z = pkh2(pv[4], pv[5]); pp.w = pkh2(pv[6], pv[7]);
            *(uint4*)&Ps[rt * PST + qd * 8] = pp;
            sum += __shfl_xor_sync(0xFFFFFFFFu, sum, 1);
            sum += __shfl_xor_sync(0xFFFFFFFFu, sum, 2);
            if (qd == 0) {
                const float sc = __expf(m_old - mx);
                l_s[rt] = l_s[rt] * sc + sum;
                m_s[rt] = mx;
                sc_s[rt] = sc;
            }
        }
        __syncthreads();

        // ---- O = O*sc + P @ V (warp: 16 rows x 32 cols) ----
        {
            const float s0 = sc_s[m0 + g];
            const float s1 = sc_s[m0 + 8 + g];
#pragma unroll
            for (int nj = 0; nj < 4; nj++) {
                oacc[nj][0] *= s0; oacc[nj][1] *= s0;
                oacc[nj][2] *= s1; oacc[nj][3] *= s1;
            }
#pragma unroll
            for (int kk = 0; kk < 2; kk++) {
                u32 pa[4];
                ldm_x4(pAddr + kk * 32, pa);
                u32 vb0[4], vb1[4];
                ldm_x4_t(vAddr + kk * 16 * QKS * 2, vb0);
                ldm_x4_t(vAddr + (kk * 16 * QKS + 16) * 2, vb1);
                mma16816(oacc[0], pa, vb0[0], vb0[1]);
                mma16816(oacc[1], pa, vb0[2], vb0[3]);
                mma16816(oacc[2], pa, vb1[0], vb1[1]);
                mma16816(oacc[3], pa, vb1[2], vb1[3]);
            }
        }
    }

    // ---- normalize + store fp16 into out-proj A buffer ----
    {
        const float li0 = 1.0f / l_s[m0 + g];
        const float li1 = 1.0f / l_s[m0 + 8 + g];
        __half* base = g_ah + (size_t)(b * SEQ + q0 + m0 + g) * D_MODEL
                       + h * DHEAD + wn * 32;
#pragma unroll
        for (int nj = 0; nj < 4; nj++) {
            const int col = nj * 8 + 2 * t4;
            *(u32*)(base + col) = pkh2(oacc[nj][0] * li0, oacc[nj][1] * li0);
            *(u32*)(base + 8 * D_MODEL + col) = pkh2(oacc[nj][2] * li1, oacc[nj][3] * li1);
        }
    }
}

// ---------------------------------------------------------------------------
extern "C" void kernel_launch(void* const* d_in, const int* in_sizes, int n_in,
                              void* d_out, int out_size)
{
    const float* hs  = (const float*)d_in[0];
    const float* Wq  = (const float*)d_in[1];
    const float* Wk  = (const float*)d_in[2];
    const float* Wv  = (const float*)d_in[3];
    const float* Wo  = (const float*)d_in[4];
    const float* bo  = (const float*)d_in[5];
    const float* Kbg = (const float*)d_in[6];
    const float* Vbg = (const float*)d_in[7];
    float* out = (float*)d_out;

    // 0) weight transpose + fp16 convert; activation fp16 convert (writes g_xh
    //    from device code — device globals must never cross the host boundary)
    dim3 gw(D_MODEL / 32, D_MODEL / 32, 4);
    prep_w_kernel<<<gw, 256>>>(Wq, Wk, Wv, Wo);
    conv_kernel<<<(M_TOTAL * D_MODEL) / (256 * 8), 256>>>(hs);

    // 1) Q/K/V projections (fp16 mma.sync; Q scaled by 1/sqrt(dh))
    dim3 gqkv(D_MODEL / 128, M_TOTAL / 128, 3);
    qkv_mm_kernel<<<gqkv, 256>>>();

    // 2) attention with injected background K/V (fp16 mma.sync)
    dim3 gattn(SEQ / 64, BHEADS);
    attn_kernel<<<gattn, 256>>>(Kbg, Vbg);

    // 3) output projection + bias (fp32 out)
    dim3 gout(D_MODEL / 128, M_TOTAL / 128, 1);
    out_mm_kernel<<<gout, 256>>>(bo, out);
}

// round 14
// speedup vs baseline: 5.2078x; 1.3242x over previous
#include <cuda_runtime.h>
#include <cuda_fp16.h>
#include <cstdint>
#include <math.h>

// Problem constants
#define D_MODEL 1280
#define NHEAD   20
#define DHEAD   64
#define BATCH   4
#define SEQ     1024
#define BHEADS  (BATCH*NHEAD)      // 80
#define M_TOTAL (BATCH*SEQ)        // 4096
#define ALPHA_C 0.48f
#define SM_SCALE 0.125f

typedef uint32_t u32;

// ---------------- scratch (device globals; referenced ONLY from device code) --
__device__ __align__(16) __half g_xh[M_TOTAL * D_MODEL];   // hs fp16
__device__ __align__(16) __half g_qh[M_TOTAL * D_MODEL];   // Q * SM_SCALE, fp16
__device__ __align__(16) __half g_kh[M_TOTAL * D_MODEL];
__device__ __align__(16) __half g_vh[M_TOTAL * D_MODEL];
__device__ __align__(16) __half g_ah[M_TOTAL * D_MODEL];   // attention output fp16
__device__ __align__(16) __half g_wt[4 * D_MODEL * D_MODEL]; // W^T fp16, [w][n*K+k]

// ---------------- helpers ----------------
__device__ __forceinline__ u32 smem_u32(const void* p) {
    u32 a;
    asm("{ .reg .u64 t; cvta.to.shared.u64 t, %1; cvt.u32.u64 %0, t; }"
        : "=r"(a) : "l"(p));
    return a;
}
__device__ __forceinline__ u32 pkh2(float lo, float hi) {
    __half2 h = __floats2half2_rn(lo, hi);
    return *(u32*)&h;
}
__device__ __forceinline__ void ldm_x4(u32 addr, u32 r[4]) {
    asm volatile("ldmatrix.sync.aligned.m8n8.x4.shared.b16 {%0,%1,%2,%3}, [%4];"
                 : "=r"(r[0]), "=r"(r[1]), "=r"(r[2]), "=r"(r[3]) : "r"(addr));
}
__device__ __forceinline__ void ldm_x4_t(u32 addr, u32 r[4]) {
    asm volatile("ldmatrix.sync.aligned.m8n8.x4.trans.shared.b16 {%0,%1,%2,%3}, [%4];"
                 : "=r"(r[0]), "=r"(r[1]), "=r"(r[2]), "=r"(r[3]) : "r"(addr));
}
__device__ __forceinline__ void mma16816(float d[4], const u32 a[4], u32 b0, u32 b1) {
    asm volatile(
        "mma.sync.aligned.m16n8k16.row.col.f32.f16.f16.f32 "
        "{%0,%1,%2,%3},{%4,%5,%6,%7},{%8,%9},{%0,%1,%2,%3};"
        : "+f"(d[0]), "+f"(d[1]), "+f"(d[2]), "+f"(d[3])
        : "r"(a[0]), "r"(a[1]), "r"(a[2]), "r"(a[3]), "r"(b0), "r"(b1));
}

// ---------------- prep kernels ----------------
__global__ __launch_bounds__(256) void conv_kernel(const float* __restrict__ src)
{
    const int i = (blockIdx.x * 256 + threadIdx.x) * 8;
    float4 a = *(const float4*)(src + i);
    float4 b = *(const float4*)(src + i + 4);
    uint4 o;
    o.x = pkh2(a.x, a.y); o.y = pkh2(a.z, a.w);
    o.z = pkh2(b.x, b.y); o.w = pkh2(b.z, b.w);
    *(uint4*)(g_xh + i) = o;
}

__global__ __launch_bounds__(256) void prep_w_kernel(const float* __restrict__ Wq,
                                                     const float* __restrict__ Wk,
                                                     const float* __restrict__ Wv,
                                                     const float* __restrict__ Wo)
{
    const int w = blockIdx.z;
    const float* W = (w == 0) ? Wq : (w == 1) ? Wk : (w == 2) ? Wv : Wo;
    __half* dst = g_wt + (size_t)w * D_MODEL * D_MODEL;

    __shared__ float t[32][33];
    const int tx = threadIdx.x & 31, ty = threadIdx.x >> 5;   // 32x8
    const int n0 = blockIdx.x * 32, k0 = blockIdx.y * 32;
#pragma unroll
    for (int i = 0; i < 4; i++)
        t[ty + i * 8][tx] = W[(size_t)(k0 + ty + i * 8) * D_MODEL + n0 + tx];
    __syncthreads();
#pragma unroll
    for (int i = 0; i < 4; i++)
        dst[(size_t)(n0 + ty + i * 8) * D_MODEL + k0 + tx] =
            __float2half_rn(t[tx][ty + i * 8]);
}

// ---------------- fp16 mma.sync GEMM (proven R12) ----------------
#define AST 40
#define BST 40

__device__ __forceinline__ void mm_body(const __half* __restrict__ A,
                                        const __half* __restrict__ Bt,
                                        __half* __restrict__ Ch,
                                        float* __restrict__ Cf,
                                        const float* __restrict__ bias,
                                        const float scale)
{
    __shared__ __align__(16) __half As[128 * AST];
    __shared__ __align__(16) __half Bs[128 * BST];

    const int tid  = threadIdx.x;
    const int wid  = tid >> 5;
    const int lane = tid & 31;
    const int g    = lane >> 2;
    const int t4   = lane & 3;

    const int brow = blockIdx.y * 128;
    const int bcol = blockIdx.x * 128;

    const int wm = wid >> 1, wn = wid & 1;
    const int m0 = wm * 32, n0 = wn * 64;

    const u32 asb = smem_u32(As);
    const u32 bsb = smem_u32(Bs);

    const int lr = tid >> 1;
    const int lc = (tid & 1) * 16;
    const __half* Agp = A  + (size_t)(brow + lr) * D_MODEL + lc;
    const __half* Bgp = Bt + (size_t)(bcol + lr) * D_MODEL + lc;

    const u32 aAddr = asb + (u32)(((m0 + (lane & 15)) * AST + 8 * (lane >> 4)) * 2);
    const u32 bAddr = bsb + (u32)(((n0 + ((lane >> 4) << 3) + (lane & 7)) * BST
                                   + 8 * ((lane >> 3) & 1)) * 2);

    float acc[2][8][4];
#pragma unroll
    for (int i = 0; i < 2; i++)
#pragma unroll
        for (int j = 0; j < 8; j++)
#pragma unroll
            for (int q = 0; q < 4; q++) acc[i][j][q] = 0.f;

    for (int k0 = 0; k0 < D_MODEL; k0 += 32) {
        uint4 av0 = *(const uint4*)(Agp + k0);
        uint4 av1 = *(const uint4*)(Agp + k0 + 8);
        uint4 bv0 = *(const uint4*)(Bgp + k0);
        uint4 bv1 = *(const uint4*)(Bgp + k0 + 8);
        *(uint4*)&As[lr * AST + lc]     = av0;
        *(uint4*)&As[lr * AST + lc + 8] = av1;
        *(uint4*)&Bs[lr * BST + lc]     = bv0;
        *(uint4*)&Bs[lr * BST + lc + 8] = bv1;
        __syncthreads();

#pragma unroll
        for (int kk = 0; kk < 32; kk += 16) {
            u32 aF[2][4];
            ldm_x4(aAddr + kk * 2, aF[0]);
            ldm_x4(aAddr + (16 * AST + kk) * 2, aF[1]);
            u32 bF[4][4];
#pragma unroll
            for (int p = 0; p < 4; p++)
                ldm_x4(bAddr + (p * 16 * BST + kk) * 2, bF[p]);
#pragma unroll
            for (int mt = 0; mt < 2; mt++)
#pragma unroll
                for (int p = 0; p < 4; p++) {
                    mma16816(acc[mt][p * 2 + 0], aF[mt], bF[p][0], bF[p][1]);
                    mma16816(acc[mt][p * 2 + 1], aF[mt], bF[p][2], bF[p][3]);
                }
        }
        __syncthreads();
    }

#pragma unroll
    for (int mt = 0; mt < 2; mt++) {
        const int r0 = brow + m0 + mt * 16 + g;
#pragma unroll
        for (int nj = 0; nj < 8; nj++) {
            const int col = bcol + n0 + nj * 8 + 2 * t4;
            float* d = acc[mt][nj];
            if (Ch) {
                *(u32*)&Ch[(size_t)r0 * D_MODEL + col] = pkh2(d[0] * scale, d[1] * scale);
                *(u32*)&Ch[(size_t)(r0 + 8) * D_MODEL + col] = pkh2(d[2] * scale, d[3] * scale);
            } else {
                float2 v;
                v.x = d[0] + bias[col]; v.y = d[1] + bias[col + 1];
                *(float2*)&Cf[(size_t)r0 * D_MODEL + col] = v;
                v.x = d[2] + bias[col]; v.y = d[3] + bias[col + 1];
                *(float2*)&Cf[(size_t)(r0 + 8) * D_MODEL + col] = v;
            }
        }
    }
}

__global__ __launch_bounds__(256) void qkv_mm_kernel()
{
    const int z = blockIdx.z;
    __half* C = (z == 0) ? g_qh : (z == 1) ? g_kh : g_vh;
    mm_body(g_xh, g_wt + (size_t)z * D_MODEL * D_MODEL, C, nullptr, nullptr,
            (z == 0) ? SM_SCALE : 1.0f);
}

__global__ __launch_bounds__(256) void out_mm_kernel(const float* __restrict__ bo,
                                                     float* __restrict__ out)
{
    mm_body(g_ah, g_wt + (size_t)3 * D_MODEL * D_MODEL, nullptr, out, bo, 1.0f);
}

// ---------------- register-resident flash attention (FA2 style) ----------------
// Block = (bh, 128-q tile), 256 threads = 8 warps. Warp w owns q rows
// [16w, 16w+16) and the FULL kv width (64 per iteration) -> softmax needs no
// cross-warp traffic. S and P live in registers; P is rebuilt from S fragments
// in-register (C-frag of two adjacent n8 blocks == A-frag of next k16 MMA).
#define QS 72    // fp16 row stride for Qs
#define KVS 72   // fp16 row stride for Ks/Vs
#define KVT 64   // kv tile

__global__ __launch_bounds__(256) void attn_kernel(const float* __restrict__ Kbg,
                                                   const float* __restrict__ Vbg)
{
    __shared__ __align__(16) __half Qs[128 * QS];
    __shared__ __align__(16) __half Ks[KVT * KVS];
    __shared__ __align__(16) __half Vs[KVT * KVS];

    const int tid  = threadIdx.x;
    const int wid  = tid >> 5;
    const int lane = tid & 31;
    const int g    = lane >> 2;
    const int t4   = lane & 3;

    const int bh = blockIdx.y;
    const int b  = bh / NHEAD;
    const int h  = bh - b * NHEAD;
    const int q0 = blockIdx.x * 128;
    const int m0 = wid * 16;

    // ---- load Q tile (128 x 64 fp16; scale folded upstream) ----
    {
        const __half* qg = g_qh + (size_t)(b * SEQ + q0) * D_MODEL + h * DHEAD;
#pragma unroll
        for (int p = 0; p < 2; p++) {
            const int idx = tid + 256 * p;
            const int r = idx >> 2;
            const int c = (idx & 3) * 16;
            *(uint4*)&Qs[r * QS + c]     = *(const uint4*)(qg + (size_t)r * D_MODEL + c);
            *(uint4*)&Qs[r * QS + c + 8] = *(const uint4*)(qg + (size_t)r * D_MODEL + c + 8);
        }
    }
    __syncthreads();

    // ---- preload Q fragments (4 k-chunks of 16) ----
    u32 qa[4][4];
    {
        const u32 qsb = smem_u32(Qs);
        const u32 base = qsb + (u32)(((m0 + (lane & 15)) * QS + 8 * (lane >> 4)) * 2);
#pragma unroll
        for (int kk = 0; kk < 4; kk++) ldm_x4(base + kk * 32, qa[kk]);
    }

    const u32 ksb = smem_u32(Ks);
    const u32 vsb = smem_u32(Vs);
    // K B-frag base (non-trans; Ks rows = kv (n), cols = dh (k))
    const u32 kAddr = ksb + (u32)(((((lane >> 4) << 3) + (lane & 7)) * KVS
                                   + 8 * ((lane >> 3) & 1)) * 2);
    // V B-frag base (trans; Vs rows = kv (k), cols = dh (n))
    const u32 vAddr = vsb + (u32)(((8 * ((lane >> 3) & 1) + (lane & 7)) * KVS
                                   + 8 * (lane >> 4)) * 2);

    float oacc[8][4];
#pragma unroll
    for (int i = 0; i < 8; i++)
#pragma unroll
        for (int j = 0; j < 4; j++) oacc[i][j] = 0.f;
    float m0r = -1e30f, m1r = -1e30f, l0r = 0.f, l1r = 0.f;

    for (int it = 0; it < (2 * SEQ) / KVT; it++) {
        const int j0 = it * KVT;
        __syncthreads();   // previous iteration's K/V consumers done

        // ---- load K/V tile (64 x 64) ----
        {
            const int r = tid >> 2;
            const int c = (tid & 3) * 16;
            uint4 kv0, kv1, vv0, vv1;
            if (j0 < SEQ) {
                const size_t off = (size_t)(b * SEQ + j0 + r) * D_MODEL + h * DHEAD + c;
                kv0 = *(const uint4*)(g_kh + off);
                kv1 = *(const uint4*)(g_kh + off + 8);
                vv0 = *(const uint4*)(g_vh + off);
                vv1 = *(const uint4*)(g_vh + off + 8);
            } else {
                const size_t off = ((size_t)bh * SEQ + (j0 - SEQ + r)) * DHEAD + c;
                float4 a = *(const float4*)(Kbg + off);
                float4 d = *(const float4*)(Kbg + off + 4);
                kv0.x = pkh2(a.x * ALPHA_C, a.y * ALPHA_C);
                kv0.y = pkh2(a.z * ALPHA_C, a.w * ALPHA_C);
                kv0.z = pkh2(d.x * ALPHA_C, d.y * ALPHA_C);
                kv0.w = pkh2(d.z * ALPHA_C, d.w * ALPHA_C);
                a = *(const float4*)(Kbg + off + 8);
                d = *(const float4*)(Kbg + off + 12);
                kv1.x = pkh2(a.x * ALPHA_C, a.y * ALPHA_C);
                kv1.y = pkh2(a.z * ALPHA_C, a.w * ALPHA_C);
                kv1.z = pkh2(d.x * ALPHA_C, d.y * ALPHA_C);
                kv1.w = pkh2(d.z * ALPHA_C, d.w * ALPHA_C);
                a = *(const float4*)(Vbg + off);
                d = *(const float4*)(Vbg + off + 4);
                vv0.x = pkh2(a.x * ALPHA_C, a.y * ALPHA_C);
                vv0.y = pkh2(a.z * ALPHA_C, a.w * ALPHA_C);
                vv0.z = pkh2(d.x * ALPHA_C, d.y * ALPHA_C);
                vv0.w = pkh2(d.z * ALPHA_C, d.w * ALPHA_C);
                a = *(const float4*)(Vbg + off + 8);
                d = *(const float4*)(Vbg + off + 12);
                vv1.x = pkh2(a.x * ALPHA_C, a.y * ALPHA_C);
                vv1.y = pkh2(a.z * ALPHA_C, a.w * ALPHA_C);
                vv1.z = pkh2(d.x * ALPHA_C, d.y * ALPHA_C);
                vv1.w = pkh2(d.z * ALPHA_C, d.w * ALPHA_C);
            }
            *(uint4*)&Ks[r * KVS + c]     = kv0;
            *(uint4*)&Ks[r * KVS + c + 8] = kv1;
            *(uint4*)&Vs[r * KVS + c]     = vv0;
            *(uint4*)&Vs[r * KVS + c + 8] = vv1;
        }
        __syncthreads();

        // ---- S = Q K^T : warp computes 16 x 64 into registers ----
        float sacc[8][4];
#pragma unroll
        for (int i = 0; i < 8; i++)
#pragma unroll
            for (int j = 0; j < 4; j++) sacc[i][j] = 0.f;
#pragma unroll
        for (int kk = 0; kk < 4; kk++) {            // dh k-chunks
#pragma unroll
            for (int nb = 0; nb < 4; nb++) {        // kv 16-wide n-chunks
                u32 kb[4];
                ldm_x4(kAddr + (u32)((nb * 16 * KVS + kk * 16) * 2), kb);
                mma16816(sacc[nb * 2 + 0], qa[kk], kb[0], kb[1]);
                mma16816(sacc[nb * 2 + 1], qa[kk], kb[2], kb[3]);
            }
        }

        // ---- online softmax, fully in registers ----
        float mx0 = m0r, mx1 = m1r;
#pragma unroll
        for (int nb = 0; nb < 8; nb++) {
            mx0 = fmaxf(mx0, fmaxf(sacc[nb][0], sacc[nb][1]));
            mx1 = fmaxf(mx1, fmaxf(sacc[nb][2], sacc[nb][3]));
        }
        mx0 = fmaxf(mx0, __shfl_xor_sync(0xFFFFFFFFu, mx0, 1));
        mx0 = fmaxf(mx0, __shfl_xor_sync(0xFFFFFFFFu, mx0, 2));
        mx1 = fmaxf(mx1, __shfl_xor_sync(0xFFFFFFFFu, mx1, 1));
        mx1 = fmaxf(mx1, __shfl_xor_sync(0xFFFFFFFFu, mx1, 2));

        const float sc0 = __expf(m0r - mx0);
        const float sc1 = __expf(m1r - mx1);
        m0r = mx0; m1r = mx1;

        float sum0 = 0.f, sum1 = 0.f;
#pragma unroll
        for (int nb = 0; nb < 8; nb++) {
            sacc[nb][0] = __expf(sacc[nb][0] - mx0); sum0 += sacc[nb][0];
            sacc[nb][1] = __expf(sacc[nb][1] - mx0); sum0 += sacc[nb][1];
            sacc[nb][2] = __expf(sacc[nb][2] - mx1); sum1 += sacc[nb][2];
            sacc[nb][3] = __expf(sacc[nb][3] - mx1); sum1 += sacc[nb][3];
        }
        sum0 += __shfl_xor_sync(0xFFFFFFFFu, sum0, 1);
        sum0 += __shfl_xor_sync(0xFFFFFFFFu, sum0, 2);
        sum1 += __shfl_xor_sync(0xFFFFFFFFu, sum1, 1);
        sum1 += __shfl_xor_sync(0xFFFFFFFFu, sum1, 2);
        l0r = l0r * sc0 + sum0;
        l1r = l1r * sc1 + sum1;

        // ---- rescale O ----
#pragma unroll
        for (int nb = 0; nb < 8; nb++) {
            oacc[nb][0] *= sc0; oacc[nb][1] *= sc0;
            oacc[nb][2] *= sc1; oacc[nb][3] *= sc1;
        }

        // ---- O += P V : P A-frags built in-register from S fragments ----
#pragma unroll
        for (int kc = 0; kc < 4; kc++) {            // kv k-chunks of 16
            u32 pa[4];
            pa[0] = pkh2(sacc[kc * 2 + 0][0], sacc[kc * 2 + 0][1]);
            pa[1] = pkh2(sacc[kc * 2 + 0][2], sacc[kc * 2 + 0][3]);
            pa[2] = pkh2(sacc[kc * 2 + 1][0], sacc[kc * 2 + 1][1]);
            pa[3] = pkh2(sacc[kc * 2 + 1][2], sacc[kc * 2 + 1][3]);
#pragma unroll
            for (int dc = 0; dc < 4; dc++) {        // dh 16-wide n-chunks
                u32 vb[4];
                ldm_x4_t(vAddr + (u32)((kc * 16 * KVS + dc * 16) * 2), vb);
                mma16816(oacc[dc * 2 + 0], pa, vb[0], vb[1]);
                mma16816(oacc[dc * 2 + 1], pa, vb[2], vb[3]);
            }
        }
    }

    // ---- normalize + store fp16 into out-proj A buffer ----
    {
        const float li0 = 1.0f / l0r;
        const float li1 = 1.0f / l1r;
        __half* base = g_ah + (size_t)(b * SEQ + q0 + m0 + g) * D_MODEL + h * DHEAD;
#pragma unroll
        for (int nb = 0; nb < 8; nb++) {
            const int col = nb * 8 + 2 * t4;
            *(u32*)(base + col) = pkh2(oacc[nb][0] * li0, oacc[nb][1] * li0);
            *(u32*)(base + 8 * D_MODEL + col) = pkh2(oacc[nb][2] * li1, oacc[nb][3] * li1);
        }
    }
}

// ---------------------------------------------------------------------------
extern "C" void kernel_launch(void* const* d_in, const int* in_sizes, int n_in,
                              void* d_out, int out_size)
{
    const float* hs  = (const float*)d_in[0];
    const float* Wq  = (const float*)d_in[1];
    const float* Wk  = (const float*)d_in[2];
    const float* Wv  = (const float*)d_in[3];
    const float* Wo  = (const float*)d_in[4];
    const float* bo  = (const float*)d_in[5];
    const float* Kbg = (const float*)d_in[6];
    const float* Vbg = (const float*)d_in[7];
    float* out = (float*)d_out;

    // 0) weight transpose + fp16 convert; activation fp16 convert
    dim3 gw(D_MODEL / 32, D_MODEL / 32, 4);
    prep_w_kernel<<<gw, 256>>>(Wq, Wk, Wv, Wo);
    conv_kernel<<<(M_TOTAL * D_MODEL) / (256 * 8), 256>>>(hs);

    // 1) Q/K/V projections (fp16 mma.sync; Q scaled by 1/sqrt(dh))
    dim3 gqkv(D_MODEL / 128, M_TOTAL / 128, 3);
    qkv_mm_kernel<<<gqkv, 256>>>();

    // 2) attention (register-resident FA2, fp16 mma.sync)
    dim3 gattn(SEQ / 128, BHEADS);
    attn_kernel<<<gattn, 256>>>(Kbg, Vbg);

    // 3) output projection + bias (fp32 out)
    dim3 gout(D_MODEL / 128, M_TOTAL / 128, 1);
    out_mm_kernel<<<gout, 256>>>(bo, out);
}

// round 15
// speedup vs baseline: 6.3968x; 1.2283x over previous
#include <cuda_runtime.h>
#include <cuda_fp16.h>
#include <cstdint>
#include <math.h>

// Problem constants
#define D_MODEL 1280
#define NHEAD   20
#define DHEAD   64
#define BATCH   4
#define SEQ     1024
#define BHEADS  (BATCH*NHEAD)      // 80
#define M_TOTAL (BATCH*SEQ)        // 4096
#define ALPHA_C 0.48f
#define SM_SCALE 0.125f

typedef uint32_t u32;

// ---------------- scratch (device globals; referenced ONLY from device code) --
__device__ __align__(16) __half g_xh[M_TOTAL * D_MODEL];   // hs fp16
__device__ __align__(16) __half g_qh[M_TOTAL * D_MODEL];   // Q * SM_SCALE, fp16
__device__ __align__(16) __half g_kh[M_TOTAL * D_MODEL];
__device__ __align__(16) __half g_vh[M_TOTAL * D_MODEL];
__device__ __align__(16) __half g_ah[M_TOTAL * D_MODEL];   // attention output fp16
__device__ __align__(16) __half g_wt[4 * D_MODEL * D_MODEL]; // W^T fp16, [w][n*K+k]
__device__ __align__(16) __half g_kbh[BHEADS * SEQ * DHEAD]; // alpha*K_bg fp16
__device__ __align__(16) __half g_vbh[BHEADS * SEQ * DHEAD]; // alpha*V_bg fp16

// ---------------- helpers ----------------
__device__ __forceinline__ u32 smem_u32(const void* p) {
    u32 a;
    asm("{ .reg .u64 t; cvta.to.shared.u64 t, %1; cvt.u32.u64 %0, t; }"
        : "=r"(a) : "l"(p));
    return a;
}
__device__ __forceinline__ u32 pkh2(float lo, float hi) {
    __half2 h = __floats2half2_rn(lo, hi);
    return *(u32*)&h;
}
__device__ __forceinline__ void ldm_x4(u32 addr, u32 r[4]) {
    asm volatile("ldmatrix.sync.aligned.m8n8.x4.shared.b16 {%0,%1,%2,%3}, [%4];"
                 : "=r"(r[0]), "=r"(r[1]), "=r"(r[2]), "=r"(r[3]) : "r"(addr));
}
__device__ __forceinline__ void ldm_x4_t(u32 addr, u32 r[4]) {
    asm volatile("ldmatrix.sync.aligned.m8n8.x4.trans.shared.b16 {%0,%1,%2,%3}, [%4];"
                 : "=r"(r[0]), "=r"(r[1]), "=r"(r[2]), "=r"(r[3]) : "r"(addr));
}
__device__ __forceinline__ void mma16816(float d[4], const u32 a[4], u32 b0, u32 b1) {
    asm volatile(
        "mma.sync.aligned.m16n8k16.row.col.f32.f16.f16.f32 "
        "{%0,%1,%2,%3},{%4,%5,%6,%7},{%8,%9},{%0,%1,%2,%3};"
        : "+f"(d[0]), "+f"(d[1]), "+f"(d[2]), "+f"(d[3])
        : "r"(a[0]), "r"(a[1]), "r"(a[2]), "r"(a[3]), "r"(b0), "r"(b1));
}
__device__ __forceinline__ void cpa16(u32 s, const void* g) {
    asm volatile("cp.async.cg.shared.global [%0], [%1], 16;" :: "r"(s), "l"(g));
}
#define CP_COMMIT() asm volatile("cp.async.commit_group;" ::: "memory")
#define CP_WAIT0()  asm volatile("cp.async.wait_group 0;" ::: "memory")

// ---------------- prep kernels ----------------
__global__ __launch_bounds__(256) void conv_kernel(const float* __restrict__ src)
{
    const int i = (blockIdx.x * 256 + threadIdx.x) * 8;
    float4 a = *(const float4*)(src + i);
    float4 b = *(const float4*)(src + i + 4);
    uint4 o;
    o.x = pkh2(a.x, a.y); o.y = pkh2(a.z, a.w);
    o.z = pkh2(b.x, b.y); o.w = pkh2(b.z, b.w);
    *(uint4*)(g_xh + i) = o;
}

// alpha-scaled fp16 conversion of background K/V
__global__ __launch_bounds__(256) void conv_bg_kernel(const float* __restrict__ Kbg,
                                                      const float* __restrict__ Vbg)
{
    const int i = (blockIdx.x * 256 + threadIdx.x) * 8;
    float4 a = *(const float4*)(Kbg + i);
    float4 b = *(const float4*)(Kbg + i + 4);
    uint4 o;
    o.x = pkh2(a.x * ALPHA_C, a.y * ALPHA_C); o.y = pkh2(a.z * ALPHA_C, a.w * ALPHA_C);
    o.z = pkh2(b.x * ALPHA_C, b.y * ALPHA_C); o.w = pkh2(b.z * ALPHA_C, b.w * ALPHA_C);
    *(uint4*)(g_kbh + i) = o;
    a = *(const float4*)(Vbg + i);
    b = *(const float4*)(Vbg + i + 4);
    o.x = pkh2(a.x * ALPHA_C, a.y * ALPHA_C); o.y = pkh2(a.z * ALPHA_C, a.w * ALPHA_C);
    o.z = pkh2(b.x * ALPHA_C, b.y * ALPHA_C); o.w = pkh2(b.z * ALPHA_C, b.w * ALPHA_C);
    *(uint4*)(g_vbh + i) = o;
}

__global__ __launch_bounds__(256) void prep_w_kernel(const float* __restrict__ Wq,
                                                     const float* __restrict__ Wk,
                                                     const float* __restrict__ Wv,
                                                     const float* __restrict__ Wo)
{
    const int w = blockIdx.z;
    const float* W = (w == 0) ? Wq : (w == 1) ? Wk : (w == 2) ? Wv : Wo;
    __half* dst = g_wt + (size_t)w * D_MODEL * D_MODEL;

    __shared__ float t[32][33];
    const int tx = threadIdx.x & 31, ty = threadIdx.x >> 5;   // 32x8
    const int n0 = blockIdx.x * 32, k0 = blockIdx.y * 32;
#pragma unroll
    for (int i = 0; i < 4; i++)
        t[ty + i * 8][tx] = W[(size_t)(k0 + ty + i * 8) * D_MODEL + n0 + tx];
    __syncthreads();
#pragma unroll
    for (int i = 0; i < 4; i++)
        dst[(size_t)(n0 + ty + i * 8) * D_MODEL + k0 + tx] =
            __float2half_rn(t[tx][ty + i * 8]);
}

// ---------------- fp16 mma.sync GEMM, cp.async double-buffered ----------------
#define AST 40
#define BST 40
#define ASTG (128 * AST)   // halves per A stage
#define BSTG (128 * BST)
#define NKC  (D_MODEL / 32)   // 40 k-chunks

__device__ __forceinline__ void mm_body(const __half* __restrict__ A,
                                        const __half* __restrict__ Bt,
                                        __half* __restrict__ Ch,
                                        float* __restrict__ Cf,
                                        const float* __restrict__ bias,
                                        const float scale)
{
    __shared__ __align__(16) __half As[2 * ASTG];
    __shared__ __align__(16) __half Bs[2 * BSTG];

    const int tid  = threadIdx.x;
    const int wid  = tid >> 5;
    const int lane = tid & 31;
    const int g    = lane >> 2;
    const int t4   = lane & 3;

    const int brow = blockIdx.y * 128;
    const int bcol = blockIdx.x * 128;

    const int wm = wid >> 1, wn = wid & 1;
    const int m0 = wm * 32, n0 = wn * 64;

    const u32 asb = smem_u32(As);
    const u32 bsb = smem_u32(Bs);

    const int lr = tid >> 1;
    const int lc = (tid & 1) * 16;
    const __half* Agp = A  + (size_t)(brow + lr) * D_MODEL + lc;
    const __half* Bgp = Bt + (size_t)(bcol + lr) * D_MODEL + lc;
    const u32 aDst = asb + (u32)((lr * AST + lc) * 2);
    const u32 bDst = bsb + (u32)((lr * BST + lc) * 2);

    const u32 aAddr = asb + (u32)(((m0 + (lane & 15)) * AST + 8 * (lane >> 4)) * 2);
    const u32 bAddr = bsb + (u32)(((n0 + ((lane >> 4) << 3) + (lane & 7)) * BST
                                   + 8 * ((lane >> 3) & 1)) * 2);

    float acc[2][8][4];
#pragma unroll
    for (int i = 0; i < 2; i++)
#pragma unroll
        for (int j = 0; j < 8; j++)
#pragma unroll
            for (int q = 0; q < 4; q++) acc[i][j][q] = 0.f;

    // prefetch stage 0
    {
        cpa16(aDst, Agp);
        cpa16(aDst + 16, Agp + 8);
        cpa16(bDst, Bgp);
        cpa16(bDst + 16, Bgp + 8);
        CP_COMMIT();
    }

    for (int kt = 0; kt < NKC; kt++) {
        CP_WAIT0();
        __syncthreads();

        if (kt + 1 < NKC) {
            const int koff = (kt + 1) * 32;
            const u32 so = (u32)(((kt + 1) & 1) ? ASTG * 2 : 0);
            const u32 sob = (u32)(((kt + 1) & 1) ? BSTG * 2 : 0);
            cpa16(aDst + so, Agp + koff);
            cpa16(aDst + so + 16, Agp + koff + 8);
            cpa16(bDst + sob, Bgp + koff);
            cpa16(bDst + sob + 16, Bgp + koff + 8);
            CP_COMMIT();
        }

        const u32 aA = aAddr + (u32)((kt & 1) ? ASTG * 2 : 0);
        const u32 bA = bAddr + (u32)((kt & 1) ? BSTG * 2 : 0);
#pragma unroll
        for (int kk = 0; kk < 32; kk += 16) {
            u32 aF[2][4];
            ldm_x4(aA + kk * 2, aF[0]);
            ldm_x4(aA + (16 * AST + kk) * 2, aF[1]);
            u32 bF[4][4];
#pragma unroll
            for (int p = 0; p < 4; p++)
                ldm_x4(bA + (p * 16 * BST + kk) * 2, bF[p]);
#pragma unroll
            for (int mt = 0; mt < 2; mt++)
#pragma unroll
                for (int p = 0; p < 4; p++) {
                    mma16816(acc[mt][p * 2 + 0], aF[mt], bF[p][0], bF[p][1]);
                    mma16816(acc[mt][p * 2 + 1], aF[mt], bF[p][2], bF[p][3]);
                }
        }
    }

#pragma unroll
    for (int mt = 0; mt < 2; mt++) {
        const int r0 = brow + m0 + mt * 16 + g;
#pragma unroll
        for (int nj = 0; nj < 8; nj++) {
            const int col = bcol + n0 + nj * 8 + 2 * t4;
            float* d = acc[mt][nj];
            if (Ch) {
                *(u32*)&Ch[(size_t)r0 * D_MODEL + col] = pkh2(d[0] * scale, d[1] * scale);
                *(u32*)&Ch[(size_t)(r0 + 8) * D_MODEL + col] = pkh2(d[2] * scale, d[3] * scale);
            } else {
                float2 v;
                v.x = d[0] + bias[col]; v.y = d[1] + bias[col + 1];
                *(float2*)&Cf[(size_t)r0 * D_MODEL + col] = v;
                v.x = d[2] + bias[col]; v.y = d[3] + bias[col + 1];
                *(float2*)&Cf[(size_t)(r0 + 8) * D_MODEL + col] = v;
            }
        }
    }
}

__global__ __launch_bounds__(256) void qkv_mm_kernel()
{
    const int z = blockIdx.z;
    __half* C = (z == 0) ? g_qh : (z == 1) ? g_kh : g_vh;
    mm_body(g_xh, g_wt + (size_t)z * D_MODEL * D_MODEL, C, nullptr, nullptr,
            (z == 0) ? SM_SCALE : 1.0f);
}

__global__ __launch_bounds__(256) void out_mm_kernel(const float* __restrict__ bo,
                                                     float* __restrict__ out)
{
    mm_body(g_ah, g_wt + (size_t)3 * D_MODEL * D_MODEL, nullptr, out, bo, 1.0f);
}

// ---------------- register-resident flash attention, cp.async pipelined -------
#define QS 72    // fp16 row stride for Qs
#define KVS 72   // fp16 row stride for Ks/Vs
#define KVT 64   // kv tile
#define KVB (KVT * KVS)        // halves per stage
#define NIT ((2 * SEQ) / KVT)  // 32

__global__ __launch_bounds__(256) void attn_kernel()
{
    __shared__ __align__(16) __half Qs[128 * QS];
    __shared__ __align__(16) __half Ks[2 * KVB];
    __shared__ __align__(16) __half Vs[2 * KVB];

    const int tid  = threadIdx.x;
    const int wid  = tid >> 5;
    const int lane = tid & 31;
    const int g    = lane >> 2;
    const int t4   = lane & 3;

    const int bh = blockIdx.y;
    const int b  = bh / NHEAD;
    const int h  = bh - b * NHEAD;
    const int q0 = blockIdx.x * 128;
    const int m0 = wid * 16;

    const u32 ksb = smem_u32(Ks);
    const u32 vsb = smem_u32(Vs);

    // tile loader: 256 threads x 2 rows x 16B per tensor
    const int klr = tid >> 3;            // 0..31
    const int klc = (tid & 7) * 8;       // 0..56
    const u32 kDst = ksb + (u32)((klr * KVS + klc) * 2);
    const u32 vDst = vsb + (u32)((klr * KVS + klc) * 2);

    auto issue_tile = [&](int it) {
        const int j0 = it * KVT;
        const u32 so = (u32)((it & 1) ? KVB * 2 : 0);
#pragma unroll
        for (int p = 0; p < 2; p++) {
            const int row = klr + 32 * p;
            const __half *ks, *vs;
            if (j0 < SEQ) {
                const size_t off = (size_t)(b * SEQ + j0 + row) * D_MODEL + h * DHEAD + klc;
                ks = g_kh + off; vs = g_vh + off;
            } else {
                const size_t off = ((size_t)bh * SEQ + (j0 - SEQ + row)) * DHEAD + klc;
                ks = g_kbh + off; vs = g_vbh + off;
            }
            cpa16(kDst + so + (u32)(32 * p * KVS * 2), ks);
            cpa16(vDst + so + (u32)(32 * p * KVS * 2), vs);
        }
        CP_COMMIT();
    };

    // ---- load Q tile (128 x 64) + prefetch kv tile 0 ----
    {
        const __half* qg = g_qh + (size_t)(b * SEQ + q0) * D_MODEL + h * DHEAD;
#pragma unroll
        for (int p = 0; p < 2; p++) {
            const int idx = tid + 256 * p;
            const int r = idx >> 2;
            const int c = (idx & 3) * 16;
            *(uint4*)&Qs[r * QS + c]     = *(const uint4*)(qg + (size_t)r * D_MODEL + c);
            *(uint4*)&Qs[r * QS + c + 8] = *(const uint4*)(qg + (size_t)r * D_MODEL + c + 8);
        }
    }
    issue_tile(0);
    __syncthreads();

    // ---- preload Q fragments ----
    u32 qa[4][4];
    {
        const u32 qsb = smem_u32(Qs);
        const u32 base = qsb + (u32)(((m0 + (lane & 15)) * QS + 8 * (lane >> 4)) * 2);
#pragma unroll
        for (int kk = 0; kk < 4; kk++) ldm_x4(base + kk * 32, qa[kk]);
    }

    const u32 kAddr = ksb + (u32)(((((lane >> 4) << 3) + (lane & 7)) * KVS
                                   + 8 * ((lane >> 3) & 1)) * 2);
    const u32 vAddr = vsb + (u32)(((8 * ((lane >> 3) & 1) + (lane & 7)) * KVS
                                   + 8 * (lane >> 4)) * 2);

    float oacc[8][4];
#pragma unroll
    for (int i = 0; i < 8; i++)
#pragma unroll
        for (int j = 0; j < 4; j++) oacc[i][j] = 0.f;
    float m0r = -1e30f, m1r = -1e30f, l0r = 0.f, l1r = 0.f;

    for (int it = 0; it < NIT; it++) {
        CP_WAIT0();
        __syncthreads();
        if (it + 1 < NIT) issue_tile(it + 1);

        const u32 so = (u32)((it & 1) ? KVB * 2 : 0);
        const u32 kA = kAddr + so;
        const u32 vA = vAddr + so;

        // ---- S = Q K^T : 16 x 64 in registers ----
        float sacc[8][4];
#pragma unroll
        for (int i = 0; i < 8; i++)
#pragma unroll
            for (int j = 0; j < 4; j++) sacc[i][j] = 0.f;
#pragma unroll
        for (int kk = 0; kk < 4; kk++) {
#pragma unroll
            for (int nb = 0; nb < 4; nb++) {
                u32 kb[4];
                ldm_x4(kA + (u32)((nb * 16 * KVS + kk * 16) * 2), kb);
                mma16816(sacc[nb * 2 + 0], qa[kk], kb[0], kb[1]);
                mma16816(sacc[nb * 2 + 1], qa[kk], kb[2], kb[3]);
            }
        }

        // ---- online softmax in registers ----
        float mx0 = m0r, mx1 = m1r;
#pragma unroll
        for (int nb = 0; nb < 8; nb++) {
            mx0 = fmaxf(mx0, fmaxf(sacc[nb][0], sacc[nb][1]));
            mx1 = fmaxf(mx1, fmaxf(sacc[nb][2], sacc[nb][3]));
        }
        mx0 = fmaxf(mx0, __shfl_xor_sync(0xFFFFFFFFu, mx0, 1));
        mx0 = fmaxf(mx0, __shfl_xor_sync(0xFFFFFFFFu, mx0, 2));
        mx1 = fmaxf(mx1, __shfl_xor_sync(0xFFFFFFFFu, mx1, 1));
        mx1 = fmaxf(mx1, __shfl_xor_sync(0xFFFFFFFFu, mx1, 2));

        const float sc0 = __expf(m0r - mx0);
        const float sc1 = __expf(m1r - mx1);
        m0r = mx0; m1r = mx1;

        float sum0 = 0.f, sum1 = 0.f;
#pragma unroll
        for (int nb = 0; nb < 8; nb++) {
            sacc[nb][0] = __expf(sacc[nb][0] - mx0); sum0 += sacc[nb][0];
            sacc[nb][1] = __expf(sacc[nb][1] - mx0); sum0 += sacc[nb][1];
            sacc[nb][2] = __expf(sacc[nb][2] - mx1); sum1 += sacc[nb][2];
            sacc[nb][3] = __expf(sacc[nb][3] - mx1); sum1 += sacc[nb][3];
        }
        sum0 += __shfl_xor_sync(0xFFFFFFFFu, sum0, 1);
        sum0 += __shfl_xor_sync(0xFFFFFFFFu, sum0, 2);
        sum1 += __shfl_xor_sync(0xFFFFFFFFu, sum1, 1);
        sum1 += __shfl_xor_sync(0xFFFFFFFFu, sum1, 2);
        l0r = l0r * sc0 + sum0;
        l1r = l1r * sc1 + sum1;

#pragma unroll
        for (int nb = 0; nb < 8; nb++) {
            oacc[nb][0] *= sc0; oacc[nb][1] *= sc0;
            oacc[nb][2] *= sc1; oacc[nb][3] *= sc1;
        }

        // ---- O += P V ----
#pragma unroll
        for (int kc = 0; kc < 4; kc++) {
            u32 pa[4];
            pa[0] = pkh2(sacc[kc * 2 + 0][0], sacc[kc * 2 + 0][1]);
            pa[1] = pkh2(sacc[kc * 2 + 0][2], sacc[kc * 2 + 0][3]);
            pa[2] = pkh2(sacc[kc * 2 + 1][0], sacc[kc * 2 + 1][1]);
            pa[3] = pkh2(sacc[kc * 2 + 1][2], sacc[kc * 2 + 1][3]);
#pragma unroll
            for (int dc = 0; dc < 4; dc++) {
                u32 vb[4];
                ldm_x4_t(vA + (u32)((kc * 16 * KVS + dc * 16) * 2), vb);
                mma16816(oacc[dc * 2 + 0], pa, vb[0], vb[1]);
                mma16816(oacc[dc * 2 + 1], pa, vb[2], vb[3]);
            }
        }
    }

    // ---- normalize + store fp16 ----
    {
        const float li0 = 1.0f / l0r;
        const float li1 = 1.0f / l1r;
        __half* base = g_ah + (size_t)(b * SEQ + q0 + m0 + g) * D_MODEL + h * DHEAD;
#pragma unroll
        for (int nb = 0; nb < 8; nb++) {
            const int col = nb * 8 + 2 * t4;
            *(u32*)(base + col) = pkh2(oacc[nb][0] * li0, oacc[nb][1] * li0);
            *(u32*)(base + 8 * D_MODEL + col) = pkh2(oacc[nb][2] * li1, oacc[nb][3] * li1);
        }
    }
}

// ---------------------------------------------------------------------------
extern "C" void kernel_launch(void* const* d_in, const int* in_sizes, int n_in,
                              void* d_out, int out_size)
{
    const float* hs  = (const float*)d_in[0];
    const float* Wq  = (const float*)d_in[1];
    const float* Wk  = (const float*)d_in[2];
    const float* Wv  = (const float*)d_in[3];
    const float* Wo  = (const float*)d_in[4];
    const float* bo  = (const float*)d_in[5];
    const float* Kbg = (const float*)d_in[6];
    const float* Vbg = (const float*)d_in[7];
    float* out = (float*)d_out;

    // 0) prep: weight transpose, activation + background fp16 conversion
    dim3 gw(D_MODEL / 32, D_MODEL / 32, 4);
    prep_w_kernel<<<gw, 256>>>(Wq, Wk, Wv, Wo);
    conv_kernel<<<(M_TOTAL * D_MODEL) / (256 * 8), 256>>>(hs);
    conv_bg_kernel<<<(BHEADS * SEQ * DHEAD) / (256 * 8), 256>>>(Kbg, Vbg);

    // 1) Q/K/V projections (fp16 mma.sync, cp.async pipelined)
    dim3 gqkv(D_MODEL / 128, M_TOTAL / 128, 3);
    qkv_mm_kernel<<<gqkv, 256>>>();

    // 2) attention (register-resident FA2, cp.async pipelined)
    dim3 gattn(SEQ / 128, BHEADS);
    attn_kernel<<<gattn, 256>>>();

    // 3) output projection + bias (fp32 out)
    dim3 gout(D_MODEL / 128, M_TOTAL / 128, 1);
    out_mm_kernel<<<gout, 256>>>(bo, out);
}